// round 16
// baseline (speedup 1.0000x reference)
#include <cuda_runtime.h>
#include <cuda_fp16.h>
#include <math.h>
#include <stdint.h>

#define N_NODES 50000
#define N_EDGES 800000
#define F 128
#define NF (N_NODES * F)
#define GSZ (256 * 128)   // one gate weight matrix [2F, F]
#define SCAN_B 196        // ceil(50000/256)

// ---------------- static device scratch (no allocs allowed) ----------------
__device__ float g_S1[N_NODES * 256];
__device__ __align__(16) __half g_Yn1[N_NODES * 256];
__device__ float g_S2[N_NODES * 128];
__device__ __align__(16) __half g_Yn2[N_NODES * 128];
__device__ __align__(16) __half g_X16[NF];        // fp16 x input (layer0: x0, layer1: h'_0)
__device__ __align__(16) __half g_H16[2 * NF];    // fp16 hidden states
__device__ __align__(16) __half g_RH16[NF];       // fp16 r*h
__device__ float g_U[NF];
__device__ __align__(16) __half g_WT16[12 * GSZ]; // transposed fp16 weights [128n x 256k]
// CSR scratch
__device__ int   g_deg[N_NODES];
__device__ int   g_rowstart[N_NODES + 1];
__device__ int   g_cursor[N_NODES];
__device__ int   g_ssrc[N_EDGES];
__device__ float g_sew[N_EDGES];
__device__ int   g_bsum[SCAN_B];
__device__ int   g_boff[SCAN_B];

// ---------------- helpers ----------------
__device__ __forceinline__ float sigmoidf_(float x) { return 1.0f / (1.0f + expf(-x)); }

__device__ __forceinline__ uint32_t smem_u32(const void* p) {
    uint32_t a;
    asm("{ .reg .u64 t; cvta.to.shared.u64 t, %1; cvt.u32.u64 %0, t; }" : "=r"(a) : "l"(p));
    return a;
}
__device__ __forceinline__ void cp16(uint32_t dst, const void* src, int srcsz) {
    asm volatile("cp.async.cg.shared.global [%0], [%1], 16, %2;"
                 :: "r"(dst), "l"(src), "r"(srcsz) : "memory");
}
#define CP_COMMIT() asm volatile("cp.async.commit_group;" ::: "memory")
#define CP_WAIT(n)  asm volatile("cp.async.wait_group %0;" :: "n"(n) : "memory")

__device__ __forceinline__ void mma_f16(float& d0, float& d1, float& d2, float& d3,
                                        uint32_t a0, uint32_t a1, uint32_t a2, uint32_t a3,
                                        uint32_t b0, uint32_t b1) {
    asm volatile("mma.sync.aligned.m16n8k16.row.col.f32.f16.f16.f32 "
                 "{%0,%1,%2,%3}, {%4,%5,%6,%7}, {%8,%9}, {%0,%1,%2,%3};"
                 : "+f"(d0), "+f"(d1), "+f"(d2), "+f"(d3)
                 : "r"(a0), "r"(a1), "r"(a2), "r"(a3), "r"(b0), "r"(b1));
}

__device__ __forceinline__ void acc8_f16(float* a, uint4 v, float w) {
    float2 f0 = __half22float2(*(__half2*)&v.x);
    float2 f1 = __half22float2(*(__half2*)&v.y);
    float2 f2 = __half22float2(*(__half2*)&v.z);
    float2 f3 = __half22float2(*(__half2*)&v.w);
    a[0] += w * f0.x; a[1] += w * f0.y;
    a[2] += w * f1.x; a[3] += w * f1.y;
    a[4] += w * f2.x; a[5] += w * f2.y;
    a[6] += w * f3.x; a[7] += w * f3.y;
}
__device__ __forceinline__ void acc4_f16(float* a, uint2 v, float w) {
    float2 f0 = __half22float2(*(__half2*)&v.x);
    float2 f1 = __half22float2(*(__half2*)&v.y);
    a[0] += w * f0.x; a[1] += w * f0.y;
    a[2] += w * f1.x; a[3] += w * f1.y;
}

// ---------------- fp32 -> fp16 conversion ----------------
__global__ void f2h(const float* __restrict__ in, __half* __restrict__ out, int n4) {
    int i = blockIdx.x * blockDim.x + threadIdx.x;
    if (i >= n4) return;
    float4 v = ((const float4*)in)[i];
    __half2 a = __floats2half2_rn(v.x, v.y);
    __half2 b = __floats2half2_rn(v.z, v.w);
    uint2 pk;
    pk.x = *(uint32_t*)&a;
    pk.y = *(uint32_t*)&b;
    ((uint2*)out)[i] = pk;
}

// ---------------- CSR build ----------------
__global__ void zero_int(int* __restrict__ p, int n) {
    int i = blockIdx.x * blockDim.x + threadIdx.x;
    if (i < n) p[i] = 0;
}
__global__ void hist_dst(const int* __restrict__ dst, int* __restrict__ deg) {
    int e = blockIdx.x * blockDim.x + threadIdx.x;
    if (e < N_EDGES) atomicAdd(&deg[dst[e]], 1);
}
__global__ void scan_bsum(const int* __restrict__ deg, int* __restrict__ bsum) {
    __shared__ int ws[8];
    int i = blockIdx.x * 256 + threadIdx.x;
    int v = (i < N_NODES) ? deg[i] : 0;
#pragma unroll
    for (int o = 16; o > 0; o >>= 1) v += __shfl_down_sync(0xFFFFFFFFu, v, o);
    if ((threadIdx.x & 31) == 0) ws[threadIdx.x >> 5] = v;
    __syncthreads();
    if (threadIdx.x < 8) {
        int s = ws[threadIdx.x];
#pragma unroll
        for (int o = 4; o > 0; o >>= 1) s += __shfl_down_sync(0xFFu, s, o);
        if (threadIdx.x == 0) bsum[blockIdx.x] = s;
    }
}
__global__ void scan_boff(const int* __restrict__ bsum, int* __restrict__ boff,
                          int* __restrict__ row_start) {
    __shared__ int s[256];
    int t = threadIdx.x;
    int v = (t < SCAN_B) ? bsum[t] : 0;
    s[t] = v;
    __syncthreads();
#pragma unroll
    for (int o = 1; o < 256; o <<= 1) {
        int y = (t >= o) ? s[t - o] : 0;
        __syncthreads();
        s[t] += y;
        __syncthreads();
    }
    if (t < SCAN_B) boff[t] = s[t] - v;
    if (t == 255) row_start[N_NODES] = s[255];
}
__global__ void scan_apply(const int* __restrict__ deg, const int* __restrict__ boff,
                           int* __restrict__ row_start, int* __restrict__ cursor) {
    __shared__ int ws[8];
    int t = threadIdx.x;
    int i = blockIdx.x * 256 + t;
    int v = (i < N_NODES) ? deg[i] : 0;
    int x = v;
#pragma unroll
    for (int o = 1; o < 32; o <<= 1) {
        int y = __shfl_up_sync(0xFFFFFFFFu, x, o);
        if ((t & 31) >= o) x += y;
    }
    if ((t & 31) == 31) ws[t >> 5] = x;
    __syncthreads();
    if (t < 8) {
        int sv = ws[t];
        int tt = sv;
#pragma unroll
        for (int o = 1; o < 8; o <<= 1) {
            int y = __shfl_up_sync(0xFFu, tt, o);
            if (t >= o) tt += y;
        }
        ws[t] = tt - sv;
    }
    __syncthreads();
    if (i < N_NODES) {
        int ex = x - v + ws[t >> 5] + boff[blockIdx.x];
        row_start[i] = ex;
        cursor[i] = ex;
    }
}
__global__ void scatter_edges(const int* __restrict__ src, const int* __restrict__ dst,
                              const float* __restrict__ ew, int* __restrict__ cursor,
                              int* __restrict__ ssrc, float* __restrict__ sew) {
    int e = blockIdx.x * blockDim.x + threadIdx.x;
    if (e >= N_EDGES) return;
    int d = dst[e];
    int p = atomicAdd(&cursor[d], 1);
    ssrc[p] = src[e];
    sew[p] = ew[e];
}

// ---------------- fused agg + gates r,u (stage 1) ----------------
// r=sig(S1+agg+b_r), u=sig(S1+agg+b_u); RH16=r*h fp16 (lanes 0-15), U=u (lanes 16-31)
__global__ void __launch_bounds__(256) csr_agg_ru(
    const int* __restrict__ rs, const int* __restrict__ ssrc,
    const float* __restrict__ sew, const __half* __restrict__ Yn,
    const float* __restrict__ S1, const float* __restrict__ bias_ru,
    const float* __restrict__ h, __half* __restrict__ RH16, float* __restrict__ U)
{
    int node = (blockIdx.x * blockDim.x + threadIdx.x) >> 5;
    if (node >= N_NODES) return;
    int lane = threadIdx.x & 31;
    int p0 = rs[node], p1 = rs[node + 1];
    float acc[8];
#pragma unroll
    for (int j = 0; j < 8; j++) acc[j] = 0.f;

    int p = p0;
    for (; p + 1 < p1; p += 2) {
        int s0 = __ldg(&ssrc[p]),  s1 = __ldg(&ssrc[p + 1]);
        float w0 = __ldg(&sew[p]), w1 = __ldg(&sew[p + 1]);
        uint4 v0 = __ldg((const uint4*)(Yn + (size_t)s0 * 256) + lane);
        uint4 v1 = __ldg((const uint4*)(Yn + (size_t)s1 * 256) + lane);
        acc8_f16(acc, v0, w0);
        acc8_f16(acc, v1, w1);
    }
    if (p < p1) {
        int s0 = __ldg(&ssrc[p]);
        float w0 = __ldg(&sew[p]);
        uint4 v0 = __ldg((const uint4*)(Yn + (size_t)s0 * 256) + lane);
        acc8_f16(acc, v0, w0);
    }

    int col = lane * 8;
    const float4* sp = (const float4*)(S1 + (size_t)node * 256 + col);
    float4 sa = sp[0], sb = sp[1];
    float4 ba = __ldg((const float4*)(bias_ru + col));
    float4 bb = __ldg((const float4*)(bias_ru + col) + 1);
    float g0 = sigmoidf_(sa.x + acc[0] + ba.x);
    float g1 = sigmoidf_(sa.y + acc[1] + ba.y);
    float g2 = sigmoidf_(sa.z + acc[2] + ba.z);
    float g3 = sigmoidf_(sa.w + acc[3] + ba.w);
    float g4 = sigmoidf_(sb.x + acc[4] + bb.x);
    float g5 = sigmoidf_(sb.y + acc[5] + bb.y);
    float g6 = sigmoidf_(sb.z + acc[6] + bb.z);
    float g7 = sigmoidf_(sb.w + acc[7] + bb.w);

    int f = (lane & 15) * 8;
    if (lane < 16) {   // r-half: RH16 = fp16(r * h)
        const float4* hp = (const float4*)(h + (size_t)node * 128 + f);
        float4 h0 = hp[0], h1 = hp[1];
        __half2 q0 = __floats2half2_rn(g0 * h0.x, g1 * h0.y);
        __half2 q1 = __floats2half2_rn(g2 * h0.z, g3 * h0.w);
        __half2 q2 = __floats2half2_rn(g4 * h1.x, g5 * h1.y);
        __half2 q3 = __floats2half2_rn(g6 * h1.z, g7 * h1.w);
        uint4 pk;
        pk.x = *(uint32_t*)&q0; pk.y = *(uint32_t*)&q1;
        pk.z = *(uint32_t*)&q2; pk.w = *(uint32_t*)&q3;
        *(uint4*)(RH16 + (size_t)node * 128 + f) = pk;
    } else {           // u-half
        float4* op = (float4*)(U + (size_t)node * 128 + f);
        op[0] = make_float4(g0, g1, g2, g3);
        op[1] = make_float4(g4, g5, g6, g7);
    }
}

// ---------------- fused agg + finalize (stage 2) ----------------
// c=sig(S2+agg+b_c); h' = u*h + (1-u)*c; also fp16 copy for next layer's x
__global__ void __launch_bounds__(256) csr_agg_fin(
    const int* __restrict__ rs, const int* __restrict__ ssrc,
    const float* __restrict__ sew, const __half* __restrict__ Yn,
    const float* __restrict__ S2, const float* __restrict__ bc,
    const float* __restrict__ h, const float* __restrict__ U,
    float* __restrict__ out_layer, float* __restrict__ out_extra,
    __half* __restrict__ out_h16)
{
    int node = (blockIdx.x * blockDim.x + threadIdx.x) >> 5;
    if (node >= N_NODES) return;
    int lane = threadIdx.x & 31;
    int p0 = rs[node], p1 = rs[node + 1];
    float acc[4];
#pragma unroll
    for (int j = 0; j < 4; j++) acc[j] = 0.f;

    int p = p0;
    for (; p + 1 < p1; p += 2) {
        int s0 = __ldg(&ssrc[p]),  s1 = __ldg(&ssrc[p + 1]);
        float w0 = __ldg(&sew[p]), w1 = __ldg(&sew[p + 1]);
        uint2 v0 = __ldg((const uint2*)(Yn + (size_t)s0 * 128) + lane);
        uint2 v1 = __ldg((const uint2*)(Yn + (size_t)s1 * 128) + lane);
        acc4_f16(acc, v0, w0);
        acc4_f16(acc, v1, w1);
    }
    if (p < p1) {
        int s0 = __ldg(&ssrc[p]);
        float w0 = __ldg(&sew[p]);
        uint2 v0 = __ldg((const uint2*)(Yn + (size_t)s0 * 128) + lane);
        acc4_f16(acc, v0, w0);
    }

    int f = lane * 4;
    float4 s = *(const float4*)(S2 + (size_t)node * 128 + f);
    float4 b = __ldg((const float4*)(bc + f));
    float4 u = *(const float4*)(U + (size_t)node * 128 + f);
    float4 hh = *(const float4*)(h + (size_t)node * 128 + f);
    float c0 = sigmoidf_(s.x + acc[0] + b.x);
    float c1 = sigmoidf_(s.y + acc[1] + b.y);
    float c2 = sigmoidf_(s.z + acc[2] + b.z);
    float c3 = sigmoidf_(s.w + acc[3] + b.w);
    float4 hn = make_float4(u.x * hh.x + (1.f - u.x) * c0,
                            u.y * hh.y + (1.f - u.y) * c1,
                            u.z * hh.z + (1.f - u.z) * c2,
                            u.w * hh.w + (1.f - u.w) * c3);
    *(float4*)(out_layer + (size_t)node * 128 + f) = hn;
    if (out_extra) *(float4*)(out_extra + (size_t)node * 128 + f) = hn;
    if (out_h16) {
        __half2 q0 = __floats2half2_rn(hn.x, hn.y);
        __half2 q1 = __floats2half2_rn(hn.z, hn.w);
        uint2 pk;
        pk.x = *(uint32_t*)&q0; pk.y = *(uint32_t*)&q1;
        *(uint2*)(out_h16 + (size_t)node * 128 + f) = pk;
    }
}

// ---------------- weight transpose -> fp16 ----------------
__global__ void transpose_w(const float* __restrict__ Ws, const float* __restrict__ Wn,
                            __half* __restrict__ WT) {
    int mat = blockIdx.y;
    int l = mat / 6, sn = (mat / 3) & 1, g = mat % 3;
    const float* src = (sn ? Wn : Ws) + ((size_t)l * 3 + g) * GSZ;
    __half* dst = WT + (size_t)mat * GSZ;
    int i = blockIdx.x * blockDim.x + threadIdx.x;
    if (i < GSZ) {
        int n = i >> 8; int k = i & 255;
        dst[i] = __float2half_rn(src[k * 128 + n]);
    }
}

// ---------------- tensor-core GEMM via mma.sync fp16 (fp32 accumulate) ----------------
// C[m, colOff:+128] = concat(A0,A1)[m, 0:256] @ WT_mat^T ; fp16 operands
#define TS 40                               // smem row stride in halves (80B, conflict-free)
#define TILE_HB (128 * TS * 2)              // one tile buffer bytes (10240)

__global__ void __launch_bounds__(256) gemm_tc(
    const __half* __restrict__ A0, const __half* __restrict__ A1,
    const __half* __restrict__ BTself, const __half* __restrict__ BTneigh,
    int half_, float* __restrict__ Cself, __half* __restrict__ Cneigh, int ldc)
{
    extern __shared__ __half smem[];
    __half* sA[2] = { smem,                 smem + 128 * TS };
    __half* sB[2] = { smem + 2 * 128 * TS,  smem + 3 * 128 * TS };
    uint32_t uA[2] = { smem_u32(sA[0]), smem_u32(sA[1]) };
    uint32_t uB[2] = { smem_u32(sB[0]), smem_u32(sB[1]) };

    int tid = threadIdx.x, wid = tid >> 5, lid = tid & 31;
    int lr = lid >> 2, lc = lid & 3;
    int m0 = blockIdx.x * 128;
    int by = blockIdx.y;
    bool is_self = (by < half_);
    const __half* BT;
    int colOff;
    if (is_self) { BT = BTself + (size_t)by * GSZ;            colOff = by * 128; }
    else         { BT = BTneigh + (size_t)(by - half_) * GSZ; colOff = (by - half_) * 128; }

    int wm = wid & 1, wn = wid >> 1;       // warp tile: rows 64*wm, cols 32*wn

    float acc[4][4][4];
#pragma unroll
    for (int mt = 0; mt < 4; mt++)
#pragma unroll
        for (int nt = 0; nt < 4; nt++)
#pragma unroll
            for (int j = 0; j < 4; j++) acc[mt][nt][j] = 0.f;

    // one k-chunk = 32 halves = 64B per row; 4 cp16 per row; 512 per tile; 2/thread
    auto copy_tile = [&](int kt, int b) {
        const __half* A = (kt < 4) ? A0 : A1;
        int kb = (kt & 3) * 32;
#pragma unroll
        for (int i = 0; i < 2; i++) {
            int c = tid + i * 256;          // 0..511
            int row = c >> 2, q = c & 3;    // q: 16B chunk (8 halves)
            int gr = m0 + row;
            int sz = (gr < N_NODES) ? 16 : 0;
            cp16(uA[b] + (uint32_t)(row * TS + q * 8) * 2,
                 A + (size_t)gr * 128 + kb + q * 8, sz);
            cp16(uB[b] + (uint32_t)(row * TS + q * 8) * 2,
                 BT + (size_t)row * 256 + kt * 32 + q * 8, 16);
        }
    };

    copy_tile(0, 0);
    CP_COMMIT();

    for (int kt = 0; kt < 8; kt++) {
        int b = kt & 1;
        if (kt < 7) { copy_tile(kt + 1, b ^ 1); CP_COMMIT(); CP_WAIT(1); }
        else        { CP_WAIT(0); }
        __syncthreads();

        const __half* As = sA[b];
        const __half* Bs = sB[b];
#pragma unroll
        for (int s = 0; s < 2; s++) {       // two k16 steps per 32-chunk
            int k0 = s * 16 + 2 * lc;
            uint32_t bf[4][2];
#pragma unroll
            for (int nt = 0; nt < 4; nt++) {
                int nb = 32 * wn + 8 * nt + lr;
                bf[nt][0] = *(const uint32_t*)&Bs[nb * TS + k0];
                bf[nt][1] = *(const uint32_t*)&Bs[nb * TS + k0 + 8];
            }
#pragma unroll
            for (int mt = 0; mt < 4; mt++) {
                int rb = 64 * wm + 16 * mt;
                uint32_t a0 = *(const uint32_t*)&As[(rb + lr) * TS + k0];
                uint32_t a1 = *(const uint32_t*)&As[(rb + 8 + lr) * TS + k0];
                uint32_t a2 = *(const uint32_t*)&As[(rb + lr) * TS + k0 + 8];
                uint32_t a3 = *(const uint32_t*)&As[(rb + 8 + lr) * TS + k0 + 8];
#pragma unroll
                for (int nt = 0; nt < 4; nt++)
                    mma_f16(acc[mt][nt][0], acc[mt][nt][1], acc[mt][nt][2], acc[mt][nt][3],
                            a0, a1, a2, a3, bf[nt][0], bf[nt][1]);
            }
        }
        __syncthreads();
    }

#pragma unroll
    for (int mt = 0; mt < 4; mt++) {
        int r0 = m0 + 64 * wm + 16 * mt + lr;
#pragma unroll
        for (int nt = 0; nt < 4; nt++) {
            int col = colOff + 32 * wn + 8 * nt + 2 * lc;
            if (is_self) {
                if (r0 < N_NODES)
                    *(float2*)(Cself + (size_t)r0 * ldc + col) =
                        make_float2(acc[mt][nt][0], acc[mt][nt][1]);
                if (r0 + 8 < N_NODES)
                    *(float2*)(Cself + (size_t)(r0 + 8) * ldc + col) =
                        make_float2(acc[mt][nt][2], acc[mt][nt][3]);
            } else {
                if (r0 < N_NODES) {
                    __half2 q = __floats2half2_rn(acc[mt][nt][0], acc[mt][nt][1]);
                    *(__half2*)(Cneigh + (size_t)r0 * ldc + col) = q;
                }
                if (r0 + 8 < N_NODES) {
                    __half2 q = __floats2half2_rn(acc[mt][nt][2], acc[mt][nt][3]);
                    *(__half2*)(Cneigh + (size_t)(r0 + 8) * ldc + col) = q;
                }
            }
        }
    }
}

// ---------------- launch ----------------
extern "C" void kernel_launch(void* const* d_in, const int* in_sizes, int n_in,
                              void* d_out, int out_size)
{
    const float* x0   = (const float*)d_in[0];
    const float* hst  = (const float*)d_in[1];
    const int*   src  = (const int*)d_in[2];
    const int*   dst  = (const int*)d_in[3];
    const float* ew   = (const float*)d_in[4];
    const float* Ws   = (const float*)d_in[5];
    const float* Wn   = (const float*)d_in[6];
    const float* bias = (const float*)d_in[7];
    float* out = (float*)d_out;

    float *S1, *S2, *U, *SEW;
    __half *Yn1, *Yn2, *X16, *H16, *RH16, *WT16;
    int *DEG, *RS, *CUR, *SSRC, *BSUM, *BOFF;
    cudaGetSymbolAddress((void**)&S1,   g_S1);
    cudaGetSymbolAddress((void**)&Yn1,  g_Yn1);
    cudaGetSymbolAddress((void**)&S2,   g_S2);
    cudaGetSymbolAddress((void**)&Yn2,  g_Yn2);
    cudaGetSymbolAddress((void**)&X16,  g_X16);
    cudaGetSymbolAddress((void**)&H16,  g_H16);
    cudaGetSymbolAddress((void**)&RH16, g_RH16);
    cudaGetSymbolAddress((void**)&U,    g_U);
    cudaGetSymbolAddress((void**)&WT16, g_WT16);
    cudaGetSymbolAddress((void**)&DEG,  g_deg);
    cudaGetSymbolAddress((void**)&RS,   g_rowstart);
    cudaGetSymbolAddress((void**)&CUR,  g_cursor);
    cudaGetSymbolAddress((void**)&SSRC, g_ssrc);
    cudaGetSymbolAddress((void**)&SEW,  g_sew);
    cudaGetSymbolAddress((void**)&BSUM, g_bsum);
    cudaGetSymbolAddress((void**)&BOFF, g_boff);

    const int SMEM_SZ = 4 * TILE_HB;   // 40960 B
    cudaFuncSetAttribute(gemm_tc, cudaFuncAttributeMaxDynamicSharedMemorySize, SMEM_SZ);

    const int mtiles = (N_NODES + 127) / 128;
    const int agg_blocks = (N_NODES * 32 + 255) / 256;
    const int eb = (N_EDGES + 255) / 256;

    // ---- prep: fp16 conversions, weight transpose, CSR build ----
    f2h<<<(NF / 4 + 255) / 256, 256>>>(x0, X16, NF / 4);
    f2h<<<(2 * NF / 4 + 255) / 256, 256>>>(hst, H16, 2 * NF / 4);
    transpose_w<<<dim3((GSZ + 255) / 256, 12), 256>>>(Ws, Wn, WT16);
    zero_int<<<(N_NODES + 255) / 256, 256>>>(DEG, N_NODES);
    hist_dst<<<eb, 256>>>(dst, DEG);
    scan_bsum<<<SCAN_B, 256>>>(DEG, BSUM);
    scan_boff<<<1, 256>>>(BSUM, BOFF, RS);
    scan_apply<<<SCAN_B, 256>>>(DEG, BOFF, RS, CUR);
    scatter_edges<<<eb, 256>>>(src, dst, ew, CUR, SSRC, SEW);

    for (int l = 0; l < 2; l++) {
        const __half* hl16 = H16 + (size_t)l * NF;
        const float*  hl   = hst + (size_t)l * NF;
        const __half* BTs  = WT16 + (size_t)((l * 2 + 0) * 3) * GSZ;
        const __half* BTn  = WT16 + (size_t)((l * 2 + 1) * 3) * GSZ;
        const float* b_ru  = bias + (size_t)l * 384;          // [b_r | b_u]
        const float* b_c   = bias + (size_t)l * 384 + 256;

        // stage 1: [S_r|S_u] fp32 and [Yn_r|Yn_u] fp16
        gemm_tc<<<dim3(mtiles, 4), 256, SMEM_SZ>>>(X16, hl16, BTs, BTn, 2, S1, Yn1, 256);
        csr_agg_ru<<<agg_blocks, 256>>>(RS, SSRC, SEW, Yn1, S1, b_ru, hl, RH16, U);

        // stage 2: S_c fp32, Yn_c fp16 with xh2 = [x, r*h]
        gemm_tc<<<dim3(mtiles, 2), 256, SMEM_SZ>>>(X16, RH16, BTs + 2 * GSZ, BTn + 2 * GSZ,
                                                   1, S2, Yn2, 128);
        float* out_layer = out + (size_t)(l + 1) * NF;
        float* out_extra = (l == 1) ? out : nullptr;
        __half* out_h16  = (l == 0) ? X16 : nullptr;   // next layer's x input
        csr_agg_fin<<<agg_blocks, 256>>>(RS, SSRC, SEW, Yn2, S2, b_c, hl, U,
                                         out_layer, out_extra, out_h16);
    }
    (void)in_sizes; (void)n_in; (void)out_size;
}